// round 14
// baseline (speedup 1.0000x reference)
#include <cuda_runtime.h>
#include <cstdint>

// x (8,3,1024,1024) f32 -> out (8,3,512,512) f32
// d_in: [0]=x, [1]=w0 (K0*512), [2]=fov0 (K0*512 i32)  -> dim2 (H, vertical)
//       [3]=w1 (K1*512), [4]=fov1 (K1*512 i32)         -> dim3 (W, horizontal)
//
// R14: R8 kernel (best: ~34us) + PRECOMPUTED METADATA.
// A tiny pre-kernel derives, once per launch: per-oh-tile {start, regular,
// wv[K]}, per-column-pair horizontal-regularity flags, wh[K], s1 — all the
// values every one of the 1536 main blocks was recomputing with ~4K LDGs +
// an extra block-wide barrier. Main kernel now reads a handful of broadcast
// loads and has ONE __syncthreads (between phases) instead of two.

#define BC     24
#define IN_H   1024
#define IN_W   1024
#define OUT_H  512
#define OUT_W  512
#define G      8            // output rows per block
#define PADW   16
#define TROW   (IN_W + 2 * PADW)
#define NTILE  (OUT_H / G)  // 64 oh-tiles

// ---- metadata scratch (written by precompute kernel every launch) ----------
__device__ int   g_vstart[NTILE];
__device__ int   g_vflag [NTILE];
__device__ float g_vw    [NTILE][12];
__device__ int   g_hok   [256];        // per column-pair (ow0 = 2t)
__device__ float g_hw    [12];
__device__ int   g_s1;

// ---------------------------------------------------------------------------
template<int K>
__global__ void precompute_kernel(const float* __restrict__ w0,
                                  const int*   __restrict__ fov0,
                                  const float* __restrict__ w1,
                                  const int*   __restrict__ fov1)
{
    const int t = threadIdx.x;                   // 0..255

    // ---- vertical: 4 threads per tile check K*G entries ----
    const int tile = t >> 2, q = t & 3;
    const int oh0  = tile * G;
    const int start = fov0[oh0];
    constexpr int PER = (K * G + 3) / 4;
    int f = 1;
#pragma unroll
    for (int n = 0; n < PER; ++n) {
        const int e = q * PER + n;
        if (e < K * G) {
            const int j = e / G, i = e % G, oh = oh0 + i;
            f &= (fov0[j * OUT_H + oh] == start + 2 * i + j);
            f &= (w0  [j * OUT_H + oh] == w0[j * OUT_H + oh0]);
        }
    }
    f &= __shfl_down_sync(0xffffffffu, f, 1);
    f &= __shfl_down_sync(0xffffffffu, f, 2);
    if (q == 0) {
        g_vflag[tile]  = f;
        g_vstart[tile] = start;
        for (int j = 0; j < K; ++j) g_vw[tile][j] = w0[j * OUT_H + oh0];
    }

    // ---- horizontal: per column pair ----
    const int ow0 = 2 * t;
    const int s1  = fov1[256] - 512;
    int ok = 1;
#pragma unroll
    for (int j = 0; j < K; ++j) {
        const float wr  = w1[j * OUT_W + 256];
        const int2   fv = *reinterpret_cast<const int2*>(fov1 + j * OUT_W + ow0);
        const float2 wv = *reinterpret_cast<const float2*>(w1  + j * OUT_W + ow0);
        ok &= (fv.x == s1 + 2 * ow0 + j) & (fv.y == s1 + 2 * ow0 + 2 + j);
        ok &= (wv.x == wr) & (wv.y == wr);
    }
    g_hok[t] = ok;
    if (t < K) g_hw[t] = w1[t * OUT_W + 256];
    if (t == 0) g_s1 = s1;
}

// ---------------------------------------------------------------------------
template<int K, int O>
__device__ __forceinline__
void hfast_rows(const float tile[G][TROW], int wstart,
                const float* __restrict__ wh,
                float* __restrict__ outp)
{
    constexpr int NQ = (K + 8) / 4;
#pragma unroll
    for (int i = 0; i < G; ++i) {
        const float4* rp = reinterpret_cast<const float4*>(tile[i] + PADW) + wstart;
        float r[NQ * 4];
#pragma unroll
        for (int q = 0; q < NQ; ++q) {
            const float4 v = rp[q];
            r[4 * q + 0] = v.x; r[4 * q + 1] = v.y;
            r[4 * q + 2] = v.z; r[4 * q + 3] = v.w;
        }
        float a0 = 0.f, a1 = 0.f;
#pragma unroll
        for (int j = 0; j < K; ++j) {
            a0 += wh[j] * r[O + j];
            a1 += wh[j] * r[O + 2 + j];
        }
        float2 res; res.x = a0; res.y = a1;
        *reinterpret_cast<float2*>(outp + (size_t)i * OUT_W) = res;
    }
}

// ---------------------------------------------------------------------------
template<int K>
__global__ __launch_bounds__(256, 5)
void fused_stream_kernel(const float* __restrict__ x,
                         const float* __restrict__ w0,
                         const int*   __restrict__ fov0,
                         const float* __restrict__ w1,
                         const int*   __restrict__ fov1,
                         float*       __restrict__ out)
{
    __shared__ float tile[G][TROW];

    const int t   = threadIdx.x;
    const int bc  = blockIdx.y;
    const int oh0 = blockIdx.x * G;

    const float4* xb = reinterpret_cast<const float4*>(x + (size_t)bc * IN_H * IN_W);

    // ---- metadata lookups (broadcast loads, L1-resident) --------------------
    const int regular = g_vflag[blockIdx.x];
    const int start   = g_vstart[blockIdx.x];
    const int hok     = g_hok[t];
    const int s1      = g_s1;

    if (regular) {
        // ---------- Phase 1a: stream K+2(G-1) rows into G accumulators ------
        constexpr int NROWS = K + 2 * (G - 1);

        float wv[K];
#pragma unroll
        for (int j = 0; j < K; ++j) wv[j] = g_vw[blockIdx.x][j];

        float4 acc[G];
#pragma unroll
        for (int m = 0; m < NROWS; ++m) {
            const float4 v = xb[(size_t)(start + m) * (IN_W / 4) + t];
#pragma unroll
            for (int i = 0; i < G; ++i) {
                const int j = m - 2 * i;
                if (j == 0) {
                    acc[i].x = wv[0] * v.x;
                    acc[i].y = wv[0] * v.y;
                    acc[i].z = wv[0] * v.z;
                    acc[i].w = wv[0] * v.w;
                } else if (j > 0 && j < K) {
                    acc[i].x += wv[j] * v.x;
                    acc[i].y += wv[j] * v.y;
                    acc[i].z += wv[j] * v.z;
                    acc[i].w += wv[j] * v.w;
                }
            }
            if (m >= K - 1 && ((m - (K - 1)) & 1) == 0) {
                const int i = (m - (K - 1)) / 2;
                reinterpret_cast<float4*>(tile[i] + PADW)[t] = acc[i];
            }
        }
    } else {
        // ---------- Phase 1b: generic gather (boundary tiles) ----------
        for (int i = 0; i < G; ++i) {
            const int oh = oh0 + i;
            float ax = 0.f, ay = 0.f, az = 0.f, aw = 0.f;
            for (int j = 0; j < K; ++j) {
                const int   r = fov0[j * OUT_H + oh];
                const float w = w0  [j * OUT_H + oh];
                const float4 v = xb[(size_t)r * (IN_W / 4) + t];
                ax += w * v.x; ay += w * v.y; az += w * v.z; aw += w * v.w;
            }
            float4 r4; r4.x = ax; r4.y = ay; r4.z = az; r4.w = aw;
            reinterpret_cast<float4*>(tile[i] + PADW)[t] = r4;
        }
    }
    __syncthreads();

    // ---------------- Phase 2: horizontal resample ---------------------------
    const int ow0 = 2 * t;
    float wh[K];
#pragma unroll
    for (int j = 0; j < K; ++j) wh[j] = g_hw[j];

    float* outp = out + ((size_t)bc * OUT_H + oh0) * OUT_W + ow0;

    if (hok) {
        const int o      = s1 & 3;               // uniform across entire grid
        const int wstart = (s1 + 4 * t) >> 2;
        if      (o == 0) hfast_rows<K, 0>(tile, wstart, wh, outp);
        else if (o == 1) hfast_rows<K, 1>(tile, wstart, wh, outp);
        else if (o == 2) hfast_rows<K, 2>(tile, wstart, wh, outp);
        else             hfast_rows<K, 3>(tile, wstart, wh, outp);
    } else {
        for (int i = 0; i < G; ++i) {
            float b0 = 0.f, b1 = 0.f;
            for (int j = 0; j < K; ++j) {
                b0 += w1[j * OUT_W + ow0]     * tile[i][PADW + fov1[j * OUT_W + ow0]];
                b1 += w1[j * OUT_W + ow0 + 1] * tile[i][PADW + fov1[j * OUT_W + ow0 + 1]];
            }
            float2 res; res.x = b0; res.y = b1;
            *reinterpret_cast<float2*>(outp + (size_t)i * OUT_W) = res;
        }
    }
}

// ---------------------------------------------------------------------------
// Fully generic fallback (runtime K0/K1), parity-split tile.
__global__ __launch_bounds__(256)
void fused_generic_kernel(const float* __restrict__ x,
                          const float* __restrict__ w0,
                          const int*   __restrict__ fov0,
                          const float* __restrict__ w1,
                          const int*   __restrict__ fov1,
                          float*       __restrict__ out,
                          int K0, int K1)
{
    __shared__ float tile[G][IN_W];
    const int t   = threadIdx.x;
    const int bc  = blockIdx.y;
    const int oh0 = blockIdx.x * G;
    const float4* xb = reinterpret_cast<const float4*>(x + (size_t)bc * IN_H * IN_W);

    for (int i = 0; i < G; ++i) {
        const int oh = oh0 + i;
        float ax = 0.f, ay = 0.f, az = 0.f, aw = 0.f;
        for (int j = 0; j < K0; ++j) {
            const int   r = fov0[j * OUT_H + oh];
            const float w = w0  [j * OUT_H + oh];
            const float4 v = xb[(size_t)r * (IN_W / 4) + t];
            ax += w * v.x; ay += w * v.y; az += w * v.z; aw += w * v.w;
        }
        float2 e; e.x = ax; e.y = az;
        float2 o; o.x = ay; o.y = aw;
        reinterpret_cast<float2*>(tile[i])[t]       = e;
        reinterpret_cast<float2*>(tile[i] + 512)[t] = o;
    }
    __syncthreads();

    float a0[G], a1[G];
#pragma unroll
    for (int i = 0; i < G; ++i) { a0[i] = 0.f; a1[i] = 0.f; }
    for (int j = 0; j < K1; ++j) {
        const float w_a = w1  [j * OUT_W + t];
        const float w_b = w1  [j * OUT_W + t + 256];
        const int   f_a = fov1[j * OUT_W + t];
        const int   f_b = fov1[j * OUT_W + t + 256];
        const int p_a = (f_a >> 1) + ((f_a & 1) << 9);
        const int p_b = (f_b >> 1) + ((f_b & 1) << 9);
#pragma unroll
        for (int i = 0; i < G; ++i) {
            a0[i] += w_a * tile[i][p_a];
            a1[i] += w_b * tile[i][p_b];
        }
    }
#pragma unroll
    for (int i = 0; i < G; ++i) {
        float* orow = out + ((size_t)bc * OUT_H + oh0 + i) * OUT_W;
        orow[t]       = a0[i];
        orow[t + 256] = a1[i];
    }
}

// ---------------------------------------------------------------------------

template<int K>
static void launch_k(const float* x, const float* w0, const int* fov0,
                     const float* w1, const int* fov1, float* out)
{
    precompute_kernel<K><<<1, 256>>>(w0, fov0, w1, fov1);
    dim3 grid(NTILE, BC);
    fused_stream_kernel<K><<<grid, 256>>>(x, w0, fov0, w1, fov1, out);
}

extern "C" void kernel_launch(void* const* d_in, const int* in_sizes, int n_in,
                              void* d_out, int out_size)
{
    const float* x    = (const float*)d_in[0];
    const float* w0   = (const float*)d_in[1];
    const int*   fov0 = (const int*)  d_in[2];
    const float* w1   = (const float*)d_in[3];
    const int*   fov1 = (const int*)  d_in[4];
    float*       out  = (float*)d_out;

    const int K0 = in_sizes[1] / OUT_H;   // vertical taps
    const int K1 = in_sizes[3] / OUT_W;   // horizontal taps

    if (K0 == K1) {
        switch (K0) {
        case 6:  launch_k< 6>(x, w0, fov0, w1, fov1, out); return;
        case 7:  launch_k< 7>(x, w0, fov0, w1, fov1, out); return;
        case 8:  launch_k< 8>(x, w0, fov0, w1, fov1, out); return;
        case 9:  launch_k< 9>(x, w0, fov0, w1, fov1, out); return;
        case 10: launch_k<10>(x, w0, fov0, w1, fov1, out); return;
        case 11: launch_k<11>(x, w0, fov0, w1, fov1, out); return;
        case 12: launch_k<12>(x, w0, fov0, w1, fov1, out); return;
        default: break;
        }
    }
    dim3 ggrid(NTILE, BC);
    fused_generic_kernel<<<ggrid, 256>>>(x, w0, fov0, w1, fov1, out, K0, K1);
}

// round 15
// speedup vs baseline: 1.0960x; 1.0960x over previous
#include <cuda_runtime.h>
#include <cstdint>

// x (8,3,1024,1024) f32 -> out (8,3,512,512) f32
// d_in: [0]=x, [1]=w0 (K0*512), [2]=fov0 (K0*512 i32)  -> dim2 (H, vertical)
//       [3]=w1 (K1*512), [4]=fov1 (K1*512 i32)         -> dim3 (W, horizontal)
//
// R15: R8 inner loops, HALF-SIZE BLOCKS. 128 threads per block, each block
// owns (bc, oh-tile of 8, 512-column half). smem 17.4KB, ~10 blocks/SM
// co-resident (vs 5) -> cross-block phase overlap doubles -> DRAM duty up
// (the one consistent signal across R5-R14: dram% == fraction of blocks in
// phase 1). Inner loops are byte-identical in spirit to R8 (eager-init
// streaming vertical pass, aligned-LDS.128 horizontal fast path).

#define BC     24
#define IN_H   1024
#define IN_W   1024
#define OUT_H  512
#define OUT_W  512
#define G      8            // output rows per tile
#define NTILE  (OUT_H / G)  // 64
#define PADL   8            // left pad (floats)
#define TROW   544          // 8 + 512 + 24 floats per tile row
#define NC4    (TROW / 4)   // 136 f4 columns (128 main + 8 halo)

// ---------------------------------------------------------------------------
// Horizontal fast path: O = ((s1+PADL) & 3) = (s1 & 3), compile-time.
// Thread tc produces outputs (ow0, ow0+1) for all G rows.
template<int K, int O>
__device__ __forceinline__
void hfast_rows(const float tile[G][TROW], int wstart,
                const float* __restrict__ wh,
                float* __restrict__ outp)
{
    constexpr int NQ = (K + 8) / 4;       // covers rel idx O + K + 1
#pragma unroll
    for (int i = 0; i < G; ++i) {
        const float4* rp = reinterpret_cast<const float4*>(tile[i]) + wstart;
        float r[NQ * 4];
#pragma unroll
        for (int q = 0; q < NQ; ++q) {
            const float4 v = rp[q];
            r[4 * q + 0] = v.x; r[4 * q + 1] = v.y;
            r[4 * q + 2] = v.z; r[4 * q + 3] = v.w;
        }
        float a0 = 0.f, a1 = 0.f;
#pragma unroll
        for (int j = 0; j < K; ++j) {
            a0 += wh[j] * r[O + j];
            a1 += wh[j] * r[O + 2 + j];
        }
        float2 res; res.x = a0; res.y = a1;
        *reinterpret_cast<float2*>(outp + (size_t)i * OUT_W) = res;
    }
}

// ---------------------------------------------------------------------------
// Vertical streaming chain for one local f4 column (R8 pattern, eager init).
template<int K>
__device__ __forceinline__
void vchain(const float4* __restrict__ xb, int start, const float* wv,
            int gf4, int lc, float tile[G][TROW])
{
    constexpr int NROWS = K + 2 * (G - 1);
    float4 acc[G];
#pragma unroll
    for (int i = 0; i < G; ++i) { acc[i].x = acc[i].y = acc[i].z = acc[i].w = 0.f; }
#pragma unroll
    for (int m = 0; m < NROWS; ++m) {
        const float4 v = xb[(size_t)(start + m) * (IN_W / 4) + gf4];
#pragma unroll
        for (int i = 0; i < G; ++i) {
            const int j = m - 2 * i;
            if (j >= 0 && j < K) {
                acc[i].x += wv[j] * v.x;
                acc[i].y += wv[j] * v.y;
                acc[i].z += wv[j] * v.z;
                acc[i].w += wv[j] * v.w;
            }
        }
        if (m >= K - 1 && ((m - (K - 1)) & 1) == 0) {
            const int i = (m - (K - 1)) / 2;    // retire closed window
            *reinterpret_cast<float4*>(&tile[i][4 * lc]) = acc[i];
        }
    }
}

// ---------------------------------------------------------------------------
template<int K>
__global__ __launch_bounds__(128)
void fused_half_kernel(const float* __restrict__ x,
                       const float* __restrict__ w0,
                       const int*   __restrict__ fov0,
                       const float* __restrict__ w1,
                       const int*   __restrict__ fov1,
                       float*       __restrict__ out)
{
    __shared__ __align__(16) float tile[G][TROW];   // 17.4 KB

    const int t    = threadIdx.x;                   // 0..127
    const int bc   = blockIdx.y;
    const int tn   = blockIdx.x >> 1;               // oh-tile
    const int h    = blockIdx.x & 1;                // column half
    const int oh0  = tn * G;
    const int gofs = 128 * h - (PADL / 4);          // global f4 of local col 0

    const float4* xb = reinterpret_cast<const float4*>(x + (size_t)bc * IN_H * IN_W);

    // ---- vertical regularity: fov0[j][oh0+i] == start + 2i + j, w0 oh-invar.
    const int start = fov0[oh0];
    int flag = 1;
    if (t < K * G) {
        const int j  = t / G;
        const int i  = t % G;
        const int oh = oh0 + i;
        flag  = (fov0[j * OUT_H + oh] == start + 2 * i + j);
        flag &= (w0  [j * OUT_H + oh] == w0[j * OUT_H + oh0]);
    }
    const int regular = __syncthreads_and(flag);

    if (regular) {
        float wv[K];
#pragma unroll
        for (int j = 0; j < K; ++j) wv[j] = w0[j * OUT_H + oh0];

        // main column
        {
            const int gf4 = min(max(gofs + t, 0), (IN_W / 4) - 1);
            vchain<K>(xb, start, wv, gf4, t, tile);
        }
        // halo columns (8 of them) — second sequential chain, warp 0 lanes 0-7
        if (t < NC4 - 128) {
            const int lc  = 128 + t;
            const int gf4 = min(max(gofs + lc, 0), (IN_W / 4) - 1);
            vchain<K>(xb, start, wv, gf4, lc, tile);
        }
    } else {
        // boundary oh-tile: generic gather fills all NC4 columns
        for (int lc = t; lc < NC4; lc += 128) {
            const int gf4 = min(max(gofs + lc, 0), (IN_W / 4) - 1);
            for (int i = 0; i < G; ++i) {
                const int oh = oh0 + i;
                float ax = 0.f, ay = 0.f, az = 0.f, aw = 0.f;
                for (int j = 0; j < K; ++j) {
                    const int   r = fov0[j * OUT_H + oh];
                    const float w = w0  [j * OUT_H + oh];
                    const float4 v = xb[(size_t)r * (IN_W / 4) + gf4];
                    ax += w * v.x; ay += w * v.y; az += w * v.z; aw += w * v.w;
                }
                float4 r4; r4.x = ax; r4.y = ay; r4.z = az; r4.w = aw;
                *reinterpret_cast<float4*>(&tile[i][4 * lc]) = r4;
            }
        }
    }
    __syncthreads();

    // ---------------- Phase 2: horizontal resample ---------------------------
    const int ow0 = 256 * h + 2 * t;                // this thread's 2 outputs
    const int s1  = fov1[256] - 512;                // reference interior column

    float wh[K];
#pragma unroll
    for (int j = 0; j < K; ++j) wh[j] = w1[j * OUT_W + 256];

    int hok = (s1 >= -PADL);
#pragma unroll
    for (int j = 0; j < K; ++j) {
        const int2   fv = *reinterpret_cast<const int2*>(fov1 + j * OUT_W + ow0);
        const float2 wv2 = *reinterpret_cast<const float2*>(w1  + j * OUT_W + ow0);
        hok &= (fv.x == s1 + 2 * ow0 + j) & (fv.y == s1 + 2 * ow0 + 2 + j);
        hok &= (wv2.x == wh[j]) & (wv2.y == wh[j]);
    }

    float* outp = out + ((size_t)bc * OUT_H + oh0) * OUT_W + ow0;

    if (hok) {
        // local float index of window start = s1 + PADL + 4*t (h-independent)
        const int o      = s1 & 3;                  // uniform across grid
        const int wstart = (s1 + PADL + 4 * t) >> 2;
        if      (o == 0) hfast_rows<K, 0>(tile, wstart, wh, outp);
        else if (o == 1) hfast_rows<K, 1>(tile, wstart, wh, outp);
        else if (o == 2) hfast_rows<K, 2>(tile, wstart, wh, outp);
        else             hfast_rows<K, 3>(tile, wstart, wh, outp);
    } else {
        // boundary columns: mirrored indices stay near this half's edge
        const int base = 512 * h - PADL;            // global float of local 0
        for (int i = 0; i < G; ++i) {
            float b0 = 0.f, b1 = 0.f;
            for (int j = 0; j < K; ++j) {
                int l0 = fov1[j * OUT_W + ow0]     - base;
                int l1 = fov1[j * OUT_W + ow0 + 1] - base;
                l0 = min(max(l0, 0), TROW - 1);
                l1 = min(max(l1, 0), TROW - 1);
                b0 += w1[j * OUT_W + ow0]     * tile[i][l0];
                b1 += w1[j * OUT_W + ow0 + 1] * tile[i][l1];
            }
            float2 res; res.x = b0; res.y = b1;
            *reinterpret_cast<float2*>(outp + (size_t)i * OUT_W) = res;
        }
    }
}

// ---------------------------------------------------------------------------
// Fully generic fallback (runtime K0/K1), parity-split tile.
__global__ __launch_bounds__(256)
void fused_generic_kernel(const float* __restrict__ x,
                          const float* __restrict__ w0,
                          const int*   __restrict__ fov0,
                          const float* __restrict__ w1,
                          const int*   __restrict__ fov1,
                          float*       __restrict__ out,
                          int K0, int K1)
{
    __shared__ float tile[G][IN_W];
    const int t   = threadIdx.x;
    const int bc  = blockIdx.y;
    const int oh0 = blockIdx.x * G;
    const float4* xb = reinterpret_cast<const float4*>(x + (size_t)bc * IN_H * IN_W);

    for (int i = 0; i < G; ++i) {
        const int oh = oh0 + i;
        float ax = 0.f, ay = 0.f, az = 0.f, aw = 0.f;
        for (int j = 0; j < K0; ++j) {
            const int   r = fov0[j * OUT_H + oh];
            const float w = w0  [j * OUT_H + oh];
            const float4 v = xb[(size_t)r * (IN_W / 4) + t];
            ax += w * v.x; ay += w * v.y; az += w * v.z; aw += w * v.w;
        }
        float2 e; e.x = ax; e.y = az;
        float2 o; o.x = ay; o.y = aw;
        reinterpret_cast<float2*>(tile[i])[t]       = e;
        reinterpret_cast<float2*>(tile[i] + 512)[t] = o;
    }
    __syncthreads();

    float a0[G], a1[G];
#pragma unroll
    for (int i = 0; i < G; ++i) { a0[i] = 0.f; a1[i] = 0.f; }
    for (int j = 0; j < K1; ++j) {
        const float w_a = w1  [j * OUT_W + t];
        const float w_b = w1  [j * OUT_W + t + 256];
        const int   f_a = fov1[j * OUT_W + t];
        const int   f_b = fov1[j * OUT_W + t + 256];
        const int p_a = (f_a >> 1) + ((f_a & 1) << 9);
        const int p_b = (f_b >> 1) + ((f_b & 1) << 9);
#pragma unroll
        for (int i = 0; i < G; ++i) {
            a0[i] += w_a * tile[i][p_a];
            a1[i] += w_b * tile[i][p_b];
        }
    }
#pragma unroll
    for (int i = 0; i < G; ++i) {
        float* orow = out + ((size_t)bc * OUT_H + oh0 + i) * OUT_W;
        orow[t]       = a0[i];
        orow[t + 256] = a1[i];
    }
}

// ---------------------------------------------------------------------------

extern "C" void kernel_launch(void* const* d_in, const int* in_sizes, int n_in,
                              void* d_out, int out_size)
{
    const float* x    = (const float*)d_in[0];
    const float* w0   = (const float*)d_in[1];
    const int*   fov0 = (const int*)  d_in[2];
    const float* w1   = (const float*)d_in[3];
    const int*   fov1 = (const int*)  d_in[4];
    float*       out  = (float*)d_out;

    const int K0 = in_sizes[1] / OUT_H;   // vertical taps
    const int K1 = in_sizes[3] / OUT_W;   // horizontal taps

    if (K0 == K1) {
        dim3 grid(2 * NTILE, BC);         // 128 x 24 = 3072 half-blocks
        switch (K0) {
        case 6:  fused_half_kernel< 6><<<grid, 128>>>(x, w0, fov0, w1, fov1, out); return;
        case 7:  fused_half_kernel< 7><<<grid, 128>>>(x, w0, fov0, w1, fov1, out); return;
        case 8:  fused_half_kernel< 8><<<grid, 128>>>(x, w0, fov0, w1, fov1, out); return;
        case 9:  fused_half_kernel< 9><<<grid, 128>>>(x, w0, fov0, w1, fov1, out); return;
        case 10: fused_half_kernel<10><<<grid, 128>>>(x, w0, fov0, w1, fov1, out); return;
        case 11: fused_half_kernel<11><<<grid, 128>>>(x, w0, fov0, w1, fov1, out); return;
        case 12: fused_half_kernel<12><<<grid, 128>>>(x, w0, fov0, w1, fov1, out); return;
        default: break;
        }
    }
    dim3 ggrid(NTILE, BC);
    fused_generic_kernel<<<ggrid, 256>>>(x, w0, fov0, w1, fov1, out, K0, K1);
}

// round 16
// speedup vs baseline: 1.1756x; 1.0727x over previous
#include <cuda_runtime.h>
#include <cstdint>

// x (8,3,1024,1024) f32 -> out (8,3,512,512) f32
// d_in: [0]=x, [1]=w0 (K0*512), [2]=fov0 (K0*512 i32)  -> dim2 (H, vertical)
//       [3]=w1 (K1*512), [4]=fov1 (K1*512 i32)         -> dim3 (W, horizontal)
//
// R16: R8 kernel with INTRA-BLOCK SOFTWARE PIPELINING across tile halves.
//   section 1: stream rows 0..K+5, retire tile rows 0..3     -> sync
//   section 2: issue remaining 8 row-loads (tile rows 4..7), THEN phase 2 on
//              rows 0..3 (no barrier between -> phase-2a LDS/FMA executes
//              under the section-2 DRAM loads)                -> sync
//   phase 2b:  rows 4..7.
// Inner loops identical to the proven R6/R8 code. 256,5 launch bounds.

#define BC     24
#define IN_H   1024
#define IN_W   1024
#define OUT_H  512
#define OUT_W  512
#define G      8            // output rows per block
#define HG     (G / 2)
#define PADW   16
#define TROW   (IN_W + 2 * PADW)
#define NTILE  (OUT_H / G)

// ---------------------------------------------------------------------------
// Horizontal fast path for tile rows [I0, I1): O = (s1 & 3), compile-time.
template<int K, int O, int I0, int I1>
__device__ __forceinline__
void hfast_rows(const float tile[G][TROW], int wstart,
                const float* __restrict__ wh,
                float* __restrict__ outp)
{
    constexpr int NQ = (K + 8) / 4;
#pragma unroll
    for (int i = I0; i < I1; ++i) {
        const float4* rp = reinterpret_cast<const float4*>(tile[i] + PADW) + wstart;
        float r[NQ * 4];
#pragma unroll
        for (int q = 0; q < NQ; ++q) {
            const float4 v = rp[q];
            r[4 * q + 0] = v.x; r[4 * q + 1] = v.y;
            r[4 * q + 2] = v.z; r[4 * q + 3] = v.w;
        }
        float a0 = 0.f, a1 = 0.f;
#pragma unroll
        for (int j = 0; j < K; ++j) {
            a0 += wh[j] * r[O + j];
            a1 += wh[j] * r[O + 2 + j];
        }
        float2 res; res.x = a0; res.y = a1;
        *reinterpret_cast<float2*>(outp + (size_t)i * OUT_W) = res;
    }
}

template<int K, int I0, int I1>
__device__ __forceinline__
void hslow_rows(const float tile[G][TROW],
                const float* __restrict__ w1, const int* __restrict__ fov1,
                int ow0, float* __restrict__ outp)
{
    for (int i = I0; i < I1; ++i) {
        float b0 = 0.f, b1 = 0.f;
        for (int j = 0; j < K; ++j) {
            b0 += w1[j * OUT_W + ow0]     * tile[i][PADW + fov1[j * OUT_W + ow0]];
            b1 += w1[j * OUT_W + ow0 + 1] * tile[i][PADW + fov1[j * OUT_W + ow0 + 1]];
        }
        float2 res; res.x = b0; res.y = b1;
        *reinterpret_cast<float2*>(outp + (size_t)i * OUT_W) = res;
    }
}

// ---------------------------------------------------------------------------
template<int K>
__global__ __launch_bounds__(256, 5)
void fused_pipe_kernel(const float* __restrict__ x,
                       const float* __restrict__ w0,
                       const int*   __restrict__ fov0,
                       const float* __restrict__ w1,
                       const int*   __restrict__ fov1,
                       float*       __restrict__ out)
{
    __shared__ float tile[G][TROW];              // ~33 KB

    const int t   = threadIdx.x;                 // 0..255
    const int bc  = blockIdx.y;
    const int oh0 = blockIdx.x * G;

    const float4* xb = reinterpret_cast<const float4*>(x + (size_t)bc * IN_H * IN_W);

    // ---- vertical regularity: fov0[j][oh0+i] == start + 2i + j, w0 oh-invar.
    const int start = fov0[oh0];
    int flag = 1;
    if (t < K * G) {
        const int j  = t / G;
        const int i  = t % G;
        const int oh = oh0 + i;
        flag  = (fov0[j * OUT_H + oh] == start + 2 * i + j);
        flag &= (w0  [j * OUT_H + oh] == w0[j * OUT_H + oh0]);
    }
    const int regular = __syncthreads_and(flag);

    constexpr int NROWS = K + 2 * (G - 1);       // 22 for K=8
    constexpr int S1    = K + 2 * (HG - 1) + 1;  // rows in section 1 (14)

    float wv[K];
    float4 acc[G];

    if (regular) {
#pragma unroll
        for (int j = 0; j < K; ++j) wv[j] = w0[j * OUT_H + oh0];

        // ---------- section 1: rows 0..S1-1, retire tile rows 0..HG-1 -------
#pragma unroll
        for (int m = 0; m < S1; ++m) {
            const float4 v = xb[(size_t)(start + m) * (IN_W / 4) + t];
#pragma unroll
            for (int i = 0; i < G; ++i) {
                const int j = m - 2 * i;
                if (j == 0) {                    // lazy init
                    acc[i].x = wv[0] * v.x;
                    acc[i].y = wv[0] * v.y;
                    acc[i].z = wv[0] * v.z;
                    acc[i].w = wv[0] * v.w;
                } else if (j > 0 && j < K) {
                    acc[i].x += wv[j] * v.x;
                    acc[i].y += wv[j] * v.y;
                    acc[i].z += wv[j] * v.z;
                    acc[i].w += wv[j] * v.w;
                }
            }
            if (m >= K - 1 && ((m - (K - 1)) & 1) == 0) {
                const int i = (m - (K - 1)) / 2;
                if (i < HG)
                    reinterpret_cast<float4*>(tile[i] + PADW)[t] = acc[i];
            }
        }
    } else {
        // boundary tile: generic gather fills ALL rows before the first sync
        for (int i = 0; i < G; ++i) {
            const int oh = oh0 + i;
            float ax = 0.f, ay = 0.f, az = 0.f, aw = 0.f;
            for (int j = 0; j < K; ++j) {
                const int   r = fov0[j * OUT_H + oh];
                const float w = w0  [j * OUT_H + oh];
                const float4 v = xb[(size_t)r * (IN_W / 4) + t];
                ax += w * v.x; ay += w * v.y; az += w * v.z; aw += w * v.w;
            }
            float4 r4; r4.x = ax; r4.y = ay; r4.z = az; r4.w = aw;
            reinterpret_cast<float4*>(tile[i] + PADW)[t] = r4;
        }
    }
    __syncthreads();                             // tile rows 0..HG-1 ready

    // ---------- section 2 (loads issue first) + phase 2a underneath ---------
    if (regular) {
#pragma unroll
        for (int m = S1; m < NROWS; ++m) {
            const float4 v = xb[(size_t)(start + m) * (IN_W / 4) + t];
#pragma unroll
            for (int i = HG; i < G; ++i) {
                const int j = m - 2 * i;
                if (j == 0) {
                    acc[i].x = wv[0] * v.x;
                    acc[i].y = wv[0] * v.y;
                    acc[i].z = wv[0] * v.z;
                    acc[i].w = wv[0] * v.w;
                } else if (j > 0 && j < K) {
                    acc[i].x += wv[j] * v.x;
                    acc[i].y += wv[j] * v.y;
                    acc[i].z += wv[j] * v.z;
                    acc[i].w += wv[j] * v.w;
                }
            }
            if (m >= K - 1 && ((m - (K - 1)) & 1) == 0) {
                const int i = (m - (K - 1)) / 2;
                if (i >= HG)
                    reinterpret_cast<float4*>(tile[i] + PADW)[t] = acc[i];
            }
        }
    }

    // ---- phase 2 setup + rows 0..HG-1 (overlaps section-2 loads) -----------
    const int ow0 = 2 * t;
    const int s1  = fov1[256] - 512;

    float wh[K];
#pragma unroll
    for (int j = 0; j < K; ++j) wh[j] = w1[j * OUT_W + 256];

    int hok = 1;
#pragma unroll
    for (int j = 0; j < K; ++j) {
        const int2   fv = *reinterpret_cast<const int2*>(fov1 + j * OUT_W + ow0);
        const float2 wv2 = *reinterpret_cast<const float2*>(w1  + j * OUT_W + ow0);
        hok &= (fv.x == s1 + 2 * ow0 + j) & (fv.y == s1 + 2 * ow0 + 2 + j);
        hok &= (wv2.x == wh[j]) & (wv2.y == wh[j]);
    }

    float* outp = out + ((size_t)bc * OUT_H + oh0) * OUT_W + ow0;
    const int o      = s1 & 3;                   // uniform across entire grid
    const int wstart = (s1 + 4 * t) >> 2;

    if (hok) {
        if      (o == 0) hfast_rows<K, 0, 0, HG>(tile, wstart, wh, outp);
        else if (o == 1) hfast_rows<K, 1, 0, HG>(tile, wstart, wh, outp);
        else if (o == 2) hfast_rows<K, 2, 0, HG>(tile, wstart, wh, outp);
        else             hfast_rows<K, 3, 0, HG>(tile, wstart, wh, outp);
    } else {
        hslow_rows<K, 0, HG>(tile, w1, fov1, ow0, outp);
    }
    __syncthreads();                             // tile rows HG..G-1 ready

    // ---- phase 2b: rows HG..G-1 --------------------------------------------
    if (hok) {
        if      (o == 0) hfast_rows<K, 0, HG, G>(tile, wstart, wh, outp);
        else if (o == 1) hfast_rows<K, 1, HG, G>(tile, wstart, wh, outp);
        else if (o == 2) hfast_rows<K, 2, HG, G>(tile, wstart, wh, outp);
        else             hfast_rows<K, 3, HG, G>(tile, wstart, wh, outp);
    } else {
        hslow_rows<K, HG, G>(tile, w1, fov1, ow0, outp);
    }
}

// ---------------------------------------------------------------------------
// Fully generic fallback (runtime K0/K1), parity-split tile.
__global__ __launch_bounds__(256)
void fused_generic_kernel(const float* __restrict__ x,
                          const float* __restrict__ w0,
                          const int*   __restrict__ fov0,
                          const float* __restrict__ w1,
                          const int*   __restrict__ fov1,
                          float*       __restrict__ out,
                          int K0, int K1)
{
    __shared__ float tile[G][IN_W];
    const int t   = threadIdx.x;
    const int bc  = blockIdx.y;
    const int oh0 = blockIdx.x * G;
    const float4* xb = reinterpret_cast<const float4*>(x + (size_t)bc * IN_H * IN_W);

    for (int i = 0; i < G; ++i) {
        const int oh = oh0 + i;
        float ax = 0.f, ay = 0.f, az = 0.f, aw = 0.f;
        for (int j = 0; j < K0; ++j) {
            const int   r = fov0[j * OUT_H + oh];
            const float w = w0  [j * OUT_H + oh];
            const float4 v = xb[(size_t)r * (IN_W / 4) + t];
            ax += w * v.x; ay += w * v.y; az += w * v.z; aw += w * v.w;
        }
        float2 e; e.x = ax; e.y = az;
        float2 o; o.x = ay; o.y = aw;
        reinterpret_cast<float2*>(tile[i])[t]       = e;
        reinterpret_cast<float2*>(tile[i] + 512)[t] = o;
    }
    __syncthreads();

    float a0[G], a1[G];
#pragma unroll
    for (int i = 0; i < G; ++i) { a0[i] = 0.f; a1[i] = 0.f; }
    for (int j = 0; j < K1; ++j) {
        const float w_a = w1  [j * OUT_W + t];
        const float w_b = w1  [j * OUT_W + t + 256];
        const int   f_a = fov1[j * OUT_W + t];
        const int   f_b = fov1[j * OUT_W + t + 256];
        const int p_a = (f_a >> 1) + ((f_a & 1) << 9);
        const int p_b = (f_b >> 1) + ((f_b & 1) << 9);
#pragma unroll
        for (int i = 0; i < G; ++i) {
            a0[i] += w_a * tile[i][p_a];
            a1[i] += w_b * tile[i][p_b];
        }
    }
#pragma unroll
    for (int i = 0; i < G; ++i) {
        float* orow = out + ((size_t)bc * OUT_H + oh0 + i) * OUT_W;
        orow[t]       = a0[i];
        orow[t + 256] = a1[i];
    }
}

// ---------------------------------------------------------------------------

extern "C" void kernel_launch(void* const* d_in, const int* in_sizes, int n_in,
                              void* d_out, int out_size)
{
    const float* x    = (const float*)d_in[0];
    const float* w0   = (const float*)d_in[1];
    const int*   fov0 = (const int*)  d_in[2];
    const float* w1   = (const float*)d_in[3];
    const int*   fov1 = (const int*)  d_in[4];
    float*       out  = (float*)d_out;

    const int K0 = in_sizes[1] / OUT_H;   // vertical taps
    const int K1 = in_sizes[3] / OUT_W;   // horizontal taps

    dim3 grid(NTILE, BC);

    if (K0 == K1) {
        switch (K0) {
        case 6:  fused_pipe_kernel< 6><<<grid, 256>>>(x, w0, fov0, w1, fov1, out); return;
        case 7:  fused_pipe_kernel< 7><<<grid, 256>>>(x, w0, fov0, w1, fov1, out); return;
        case 8:  fused_pipe_kernel< 8><<<grid, 256>>>(x, w0, fov0, w1, fov1, out); return;
        case 9:  fused_pipe_kernel< 9><<<grid, 256>>>(x, w0, fov0, w1, fov1, out); return;
        case 10: fused_pipe_kernel<10><<<grid, 256>>>(x, w0, fov0, w1, fov1, out); return;
        case 11: fused_pipe_kernel<11><<<grid, 256>>>(x, w0, fov0, w1, fov1, out); return;
        case 12: fused_pipe_kernel<12><<<grid, 256>>>(x, w0, fov0, w1, fov1, out); return;
        default: break;
        }
    }
    fused_generic_kernel<<<grid, 256>>>(x, w0, fov0, w1, fov1, out, K0, K1);
}

// round 17
// speedup vs baseline: 1.2321x; 1.0481x over previous
#include <cuda_runtime.h>
#include <cstdint>

// x (8,3,1024,1024) f32 -> out (8,3,512,512) f32
// d_in: [0]=x, [1]=w0 (K0*512), [2]=fov0 (K0*512 i32)  -> dim2 (H, vertical)
//       [3]=w1 (K1*512), [4]=fov1 (K1*512 i32)         -> dim3 (W, horizontal)
//
// R17: the session champion (R5: rolling register window vertical pass +
// parity-split conflict-free horizontal pass, bench 35.3us) with ONE change:
// phase 2's tap loop is now compile-time K (we only take this path when
// K0==K1), so it fully unrolls — the 32 weight/index LDGs batch up front and
// 8 independent FMA chains interleave, instead of a serial runtime loop.

#define BC     24
#define IN_H   1024
#define IN_W   1024
#define OUT_H  512
#define OUT_W  512
#define G      8           // output rows per block

// ---------------------------------------------------------------------------
template<int K>
__global__ __launch_bounds__(256)
void fused_roll_kernel(const float* __restrict__ x,
                       const float* __restrict__ w0,
                       const int*   __restrict__ fov0,
                       const float* __restrict__ w1,
                       const int*   __restrict__ fov1,
                       float*       __restrict__ out)
{
    __shared__ float tile[G][IN_W];              // 32 KB, parity-permuted

    const int t   = threadIdx.x;                 // 0..255
    const int bc  = blockIdx.y;
    const int oh0 = blockIdx.x * G;

    const float4* xb = reinterpret_cast<const float4*>(x + (size_t)bc * IN_H * IN_W);

    // ---- regularity check: fov0[j][oh0+i] == start + 2i + j, w0 oh-invariant
    const int start = fov0[oh0];
    int flag = 1;
    if (t < K * G) {
        const int j  = t / G;
        const int i  = t % G;
        const int oh = oh0 + i;
        flag  = (fov0[j * OUT_H + oh] == start + 2 * i + j);
        flag &= (w0  [j * OUT_H + oh] == w0[j * OUT_H + oh0]);
    }
    const int regular = __syncthreads_and(flag);

    if (regular) {
        // ---------- Phase 1a: rolling-window vertical resample ----------
        float wv[K];
#pragma unroll
        for (int j = 0; j < K; ++j) wv[j] = w0[j * OUT_H + oh0];

        float4 win[K];
#pragma unroll
        for (int j = 0; j < K; ++j)
            win[j] = xb[(size_t)(start + j) * (IN_W / 4) + t];

#pragma unroll
        for (int i = 0; i < G; ++i) {
            float ax = 0.f, ay = 0.f, az = 0.f, aw = 0.f;
#pragma unroll
            for (int j = 0; j < K; ++j) {
                ax += wv[j] * win[j].x;
                ay += wv[j] * win[j].y;
                az += wv[j] * win[j].z;
                aw += wv[j] * win[j].w;
            }
            float2 e; e.x = ax; e.y = az;
            float2 o; o.x = ay; o.y = aw;
            reinterpret_cast<float2*>(tile[i])[t]       = e;   // even cols
            reinterpret_cast<float2*>(tile[i] + 512)[t] = o;   // odd cols

            if (i < G - 1) {
#pragma unroll
                for (int j = 0; j < K - 2; ++j) win[j] = win[j + 2];
                const int base = start + 2 * i + K;
                win[K - 2] = xb[(size_t)base       * (IN_W / 4) + t];
                win[K - 1] = xb[(size_t)(base + 1) * (IN_W / 4) + t];
            }
        }
    } else {
        // ---------- Phase 1b: generic gather (boundary blocks) ----------
        for (int i = 0; i < G; ++i) {
            const int oh = oh0 + i;
            float ax = 0.f, ay = 0.f, az = 0.f, aw = 0.f;
            for (int j = 0; j < K; ++j) {
                const int   r = fov0[j * OUT_H + oh];
                const float w = w0  [j * OUT_H + oh];
                const float4 v = xb[(size_t)r * (IN_W / 4) + t];
                ax += w * v.x;
                ay += w * v.y;
                az += w * v.z;
                aw += w * v.w;
            }
            float2 e; e.x = ax; e.y = az;
            float2 o; o.x = ay; o.y = aw;
            reinterpret_cast<float2*>(tile[i])[t]       = e;
            reinterpret_cast<float2*>(tile[i] + 512)[t] = o;
        }
    }
    __syncthreads();

    // ---------------- Phase 2: horizontal resample (compile-time K) ---------
    float a0[G], a1[G];
#pragma unroll
    for (int i = 0; i < G; ++i) { a0[i] = 0.f; a1[i] = 0.f; }

#pragma unroll
    for (int j = 0; j < K; ++j) {
        const float w_a = w1  [j * OUT_W + t];
        const float w_b = w1  [j * OUT_W + t + 256];
        const int   f_a = fov1[j * OUT_W + t];
        const int   f_b = fov1[j * OUT_W + t + 256];
        // permuted indices, computed once per tap, reused across G rows
        const int p_a = (f_a >> 1) + ((f_a & 1) << 9);
        const int p_b = (f_b >> 1) + ((f_b & 1) << 9);
#pragma unroll
        for (int i = 0; i < G; ++i) {
            a0[i] += w_a * tile[i][p_a];
            a1[i] += w_b * tile[i][p_b];
        }
    }

#pragma unroll
    for (int i = 0; i < G; ++i) {
        float* orow = out + ((size_t)bc * OUT_H + oh0 + i) * OUT_W;
        orow[t]       = a0[i];
        orow[t + 256] = a1[i];
    }
}

// ---------------------------------------------------------------------------
// Generic fallback kernel (runtime K0/K1) for shapes outside the template set.
__global__ __launch_bounds__(256)
void fused_generic_kernel(const float* __restrict__ x,
                          const float* __restrict__ w0,
                          const int*   __restrict__ fov0,
                          const float* __restrict__ w1,
                          const int*   __restrict__ fov1,
                          float*       __restrict__ out,
                          int K0, int K1)
{
    __shared__ float tile[G][IN_W];
    const int t   = threadIdx.x;
    const int bc  = blockIdx.y;
    const int oh0 = blockIdx.x * G;
    const float4* xb = reinterpret_cast<const float4*>(x + (size_t)bc * IN_H * IN_W);

    for (int i = 0; i < G; ++i) {
        const int oh = oh0 + i;
        float ax = 0.f, ay = 0.f, az = 0.f, aw = 0.f;
        for (int j = 0; j < K0; ++j) {
            const int   r = fov0[j * OUT_H + oh];
            const float w = w0  [j * OUT_H + oh];
            const float4 v = xb[(size_t)r * (IN_W / 4) + t];
            ax += w * v.x; ay += w * v.y; az += w * v.z; aw += w * v.w;
        }
        float2 e; e.x = ax; e.y = az;
        float2 o; o.x = ay; o.y = aw;
        reinterpret_cast<float2*>(tile[i])[t]       = e;
        reinterpret_cast<float2*>(tile[i] + 512)[t] = o;
    }
    __syncthreads();

    float a0[G], a1[G];
#pragma unroll
    for (int i = 0; i < G; ++i) { a0[i] = 0.f; a1[i] = 0.f; }
    for (int j = 0; j < K1; ++j) {
        const float w_a = w1  [j * OUT_W + t];
        const float w_b = w1  [j * OUT_W + t + 256];
        const int   f_a = fov1[j * OUT_W + t];
        const int   f_b = fov1[j * OUT_W + t + 256];
        const int p_a = (f_a >> 1) + ((f_a & 1) << 9);
        const int p_b = (f_b >> 1) + ((f_b & 1) << 9);
#pragma unroll
        for (int i = 0; i < G; ++i) {
            a0[i] += w_a * tile[i][p_a];
            a1[i] += w_b * tile[i][p_b];
        }
    }
#pragma unroll
    for (int i = 0; i < G; ++i) {
        float* orow = out + ((size_t)bc * OUT_H + oh0 + i) * OUT_W;
        orow[t]       = a0[i];
        orow[t + 256] = a1[i];
    }
}

// ---------------------------------------------------------------------------

extern "C" void kernel_launch(void* const* d_in, const int* in_sizes, int n_in,
                              void* d_out, int out_size)
{
    const float* x    = (const float*)d_in[0];
    const float* w0   = (const float*)d_in[1];
    const int*   fov0 = (const int*)  d_in[2];
    const float* w1   = (const float*)d_in[3];
    const int*   fov1 = (const int*)  d_in[4];
    float*       out  = (float*)d_out;

    const int K0 = in_sizes[1] / OUT_H;   // vertical taps
    const int K1 = in_sizes[3] / OUT_W;   // horizontal taps

    dim3 grid(OUT_H / G, BC);

    if (K0 == K1) {
        switch (K0) {
        case 6:  fused_roll_kernel< 6><<<grid, 256>>>(x, w0, fov0, w1, fov1, out); return;
        case 7:  fused_roll_kernel< 7><<<grid, 256>>>(x, w0, fov0, w1, fov1, out); return;
        case 8:  fused_roll_kernel< 8><<<grid, 256>>>(x, w0, fov0, w1, fov1, out); return;
        case 9:  fused_roll_kernel< 9><<<grid, 256>>>(x, w0, fov0, w1, fov1, out); return;
        case 10: fused_roll_kernel<10><<<grid, 256>>>(x, w0, fov0, w1, fov1, out); return;
        case 11: fused_roll_kernel<11><<<grid, 256>>>(x, w0, fov0, w1, fov1, out); return;
        case 12: fused_roll_kernel<12><<<grid, 256>>>(x, w0, fov0, w1, fov1, out); return;
        default: break;
        }
    }
    fused_generic_kernel<<<grid, 256>>>(x, w0, fov0, w1, fov1, out, K0, K1);
}